// round 16
// baseline (speedup 1.0000x reference)
#include <cuda_runtime.h>
#include <cuda_fp16.h>
#include <cstdint>

// Problem shape (fixed by the dataset instance)
#define BB   2
#define HH   32
#define SS   4096
#define DD   128
#define BLK  512
#define NB   (SS / BLK)          // 8
#define NCTA (BB * HH * NB)      // 512
#define NT   256
#define EPS_F 1e-6f

// Phase-1 staging: plain row-major fp16 [s][cols], 68 words (136 halves) per row
#define PST   68                            // words per s-row (272 B; 68%32==4)
#define P1ROWS 16
#define BUF_WORDS (2 * P1ROWS * PST)        // phiK tile + V tile = 2176 words
#define BUF_BYTES (BUF_WORDS * 4)           // 8704
// Phase-2 ldmatrix tiles (word = half2 pair along d, d contiguous)
#define WSTR 68    // WS2 [136][WSTR]: rows m (128=Z, 129..135=0)
#define QSTR 68    // WQ  [64][QSTR] x2 buffers

#define WS2_OFF 0
#define WQ_OFF  (136 * WSTR)                // 9248
#define WQ_BUF  (64 * QSTR)                 // 4352 words per buffer
#define SMEM_WORDS (WQ_OFF + 2 * WQ_BUF)    // 17952 (phase-1 2*2176 fits inside)
#define SMEM_BYTES (SMEM_WORDS * 4)         // 71808 B -> 2 CTAs/SM

__device__ __forceinline__ float phi_elu1(float y) {
    return y > 0.0f ? y + 1.0f : __expf(y);
}

__device__ __forceinline__ uint32_t pk2(float lo, float hi) {
    __half2 h = __floats2half2_rn(lo, hi);
    return *reinterpret_cast<uint32_t*>(&h);
}

__device__ __forceinline__ uint32_t smem_u32(const void* p) {
    uint32_t a;
    asm("{ .reg .u64 t; cvta.to.shared.u64 t, %1; cvt.u32.u64 %0, t; }"
        : "=r"(a) : "l"(p));
    return a;
}

__device__ __forceinline__ void mma_f16(float* c, const uint32_t* a, const uint32_t* b) {
    asm volatile(
        "mma.sync.aligned.m16n8k16.row.col.f32.f16.f16.f32 "
        "{%0,%1,%2,%3}, {%4,%5,%6,%7}, {%8,%9}, {%0,%1,%2,%3};\n"
        : "+f"(c[0]), "+f"(c[1]), "+f"(c[2]), "+f"(c[3])
        : "r"(a[0]), "r"(a[1]), "r"(a[2]), "r"(a[3]), "r"(b[0]), "r"(b[1]));
}

#define LDSM4(r, addr)                                                      \
    asm volatile("ldmatrix.sync.aligned.m8n8.x4.shared.b16 "                \
                 "{%0,%1,%2,%3}, [%4];"                                     \
                 : "=r"((r)[0]), "=r"((r)[1]), "=r"((r)[2]), "=r"((r)[3])   \
                 : "r"(addr))
#define LDSM4T(r, addr)                                                     \
    asm volatile("ldmatrix.sync.aligned.m8n8.x4.trans.shared.b16 "          \
                 "{%0,%1,%2,%3}, [%4];"                                     \
                 : "=r"((r)[0]), "=r"((r)[1]), "=r"((r)[2]), "=r"((r)[3])   \
                 : "r"(addr))
#define LDSM2(r, addr)                                                      \
    asm volatile("ldmatrix.sync.aligned.m8n8.x2.shared.b16 "                \
                 "{%0,%1}, [%2];"                                           \
                 : "=r"((r)[0]), "=r"((r)[1])                               \
                 : "r"(addr))

extern "C" __global__ void __launch_bounds__(NT, 2)
lin_attn_lt(const float* __restrict__ q,
            const float* __restrict__ k,
            const float* __restrict__ v,
            const float* __restrict__ sc,
            const float* __restrict__ bi,
            float* __restrict__ out)
{
    extern __shared__ uint32_t sm[];
    uint32_t* WS2   = sm + WS2_OFF;     // [136][WSTR] half2 along d; row 128 = Z
    uint32_t* stage = sm + WQ_OFF;      // phase1: 2 x (K tile + V tile); phase2: WQ x2

    const int tid  = threadIdx.x;
    const int lane = tid & 31;
    const int w    = tid >> 5;          // warp 0..7
    const int g    = lane >> 2;         // 0..7
    const int t    = lane & 3;          // 0..3

    const int c  = blockIdx.x;
    const int n  = c % NB;
    const int bh = c / NB;
    const int h  = bh % HH;
    const long gbase = ((long)bh * SS + (long)n * BLK) * DD;

    const float* qb = q + gbase;
    const float* kb = k + gbase;
    const float* vb = v + gbase;
    float*       ob = out + gbase;

    const int lrow = w;                 // producer handles s-row pair (2w, 2w+1)
    const int c4   = lane * 4;          // producer d-columns c4..c4+3
    const float4 sc4 = *(const float4*)(sc + h * DD + c4);
    const float4 bi4 = *(const float4*)(bi + h * DD + c4);

    // ====== Phase 1: S^T[m][d] = V^T x phiK  (A = V^T, B = phiK, k = s) ====
    const int wa = w & 1;               // m half (64)
    const int wb = w >> 1;              // d quarter (32)

    float acc[4][4][4];                 // [mt][dt][c]
    #pragma unroll
    for (int a = 0; a < 4; ++a)
        #pragma unroll
        for (int b = 0; b < 4; ++b)
            #pragma unroll
            for (int r = 0; r < 4; ++r) acc[a][b][r] = 0.0f;

    float4 zacc = make_float4(0.f, 0.f, 0.f, 0.f);
    float4 kv0, kv1, vv0, vv1;

#define LOADCH(ch) do {                                                     \
        const float* kc_ = kb + (long)((ch) * 16 + 2 * lrow) * DD;          \
        const float* vc_ = vb + (long)((ch) * 16 + 2 * lrow) * DD;          \
        kv0 = *(const float4*)(kc_ + c4);                                   \
        kv1 = *(const float4*)(kc_ + DD + c4);                              \
        vv0 = *(const float4*)(vc_ + c4);                                   \
        vv1 = *(const float4*)(vc_ + DD + c4);                              \
    } while (0)

    // plain row-major fp16 staging: row s, halves d contiguous (word = d,d+1)
#define STORECH(pk_, pv_) do {                                              \
        float a0 = phi_elu1(fmaf(kv0.x, sc4.x, bi4.x));                     \
        float a1 = phi_elu1(fmaf(kv0.y, sc4.y, bi4.y));                     \
        float a2 = phi_elu1(fmaf(kv0.z, sc4.z, bi4.z));                     \
        float a3 = phi_elu1(fmaf(kv0.w, sc4.w, bi4.w));                     \
        float b0 = phi_elu1(fmaf(kv1.x, sc4.x, bi4.x));                     \
        float b1 = phi_elu1(fmaf(kv1.y, sc4.y, bi4.y));                     \
        float b2 = phi_elu1(fmaf(kv1.z, sc4.z, bi4.z));                     \
        float b3 = phi_elu1(fmaf(kv1.w, sc4.w, bi4.w));                     \
        zacc.x += a0 + b0; zacc.y += a1 + b1;                               \
        zacc.z += a2 + b2; zacc.w += a3 + b3;                               \
        *(uint2*)((pk_) + (2 * lrow)     * PST + 2 * lane) =                \
            make_uint2(pk2(a0, a1), pk2(a2, a3));                           \
        *(uint2*)((pk_) + (2 * lrow + 1) * PST + 2 * lane) =                \
            make_uint2(pk2(b0, b1), pk2(b2, b3));                           \
        *(uint2*)((pv_) + (2 * lrow)     * PST + 2 * lane) =                \
            make_uint2(pk2(vv0.x, vv0.y), pk2(vv0.z, vv0.w));               \
        *(uint2*)((pv_) + (2 * lrow + 1) * PST + 2 * lane) =                \
            make_uint2(pk2(vv1.x, vv1.y), pk2(vv1.z, vv1.w));               \
    } while (0)

    // ldmatrix.trans base addresses (bytes), lane-invariant parts:
    //  A (V, [s][m]):  matrices r0..r3 = (S0M0, S0M1, S1M0, S1M1)
    //    lane l: s-row = (l>>4)*8 + (l&7), m-chunk = wa*64 + mt*16 + ((l>>3)&1)*8
    //  B (phiK, [s][d]): matrices r0..r3 = (S0D0, S1D0, S0D1, S1D1)
    //    lane l: s-row = ((l>>3)&1)*8 + (l&7), d-chunk = wb*32 + bt*16 + (l>>4)*8
    const uint32_t stage_b = smem_u32(stage);
    const int l = lane;
    const uint32_t aAb = stage_b + (uint32_t)(P1ROWS * PST * 4)             // V tile
                       + (uint32_t)(((l >> 4) * 8 + (l & 7)) * (PST * 4))
                       + (uint32_t)((wa * 64 + ((l >> 3) & 1) * 8) * 2);
    const uint32_t bBb = stage_b
                       + (uint32_t)((((l >> 3) & 1) * 8 + (l & 7)) * (PST * 4))
                       + (uint32_t)((wb * 32 + (l >> 4) * 8) * 2);

    LOADCH(0);
    STORECH(stage, stage + P1ROWS * PST);
    LOADCH(1);
    __syncthreads();

    for (int ch = 0; ch < BLK / 16; ++ch) {
        const int p = ch & 1;

        if (ch < BLK / 16 - 1) {
            uint32_t* npk = stage + (p ^ 1) * BUF_WORDS;
            STORECH(npk, npk + P1ROWS * PST);
        }
        if (ch < BLK / 16 - 2) LOADCH(ch + 2);

        const uint32_t pb = (uint32_t)(p * BUF_BYTES);
        uint32_t Bf[2][4];
        LDSM4T(Bf[0], bBb + pb);
        LDSM4T(Bf[1], bBb + pb + 32u);
        #pragma unroll
        for (int mt = 0; mt < 4; ++mt) {
            uint32_t A[4];
            LDSM4T(A, aAb + pb + (uint32_t)(mt * 32));
            mma_f16(acc[mt][0], A, &Bf[0][0]);
            mma_f16(acc[mt][1], A, &Bf[0][2]);
            mma_f16(acc[mt][2], A, &Bf[1][0]);
            mma_f16(acc[mt][3], A, &Bf[1][2]);
        }
        __syncthreads();
    }

    // ===== epilogue: S^T -> WS2[m][d-halves] (c0,c1 are d-adjacent) =====
    #pragma unroll
    for (int mt = 0; mt < 4; ++mt) {
        const int m = wa * 64 + mt * 16 + g;
        #pragma unroll
        for (int dt = 0; dt < 4; ++dt) {
            const int dw = wb * 16 + dt * 4 + t;       // d word index
            WS2[m       * WSTR + dw] = pk2(acc[mt][dt][0], acc[mt][dt][1]);
            WS2[(m + 8) * WSTR + dw] = pk2(acc[mt][dt][2], acc[mt][dt][3]);
        }
    }

    // prefetch Q chunk 0 (overlaps Z reduction)
    float4 qreg[8];
    #pragma unroll
    for (int j = 0; j < 8; ++j)
        qreg[j] = *(const float4*)(qb + (long)(lrow + 8 * j) * DD + c4);

    // reduce Z -> WS2 row 128 ; zero rows 129..135
    float* zred = (float*)stage;
    *(float4*)(zred + lrow * DD + c4) = zacc;
    __syncthreads();
    if (tid < 64) {
        float z0 = 0.0f, z1 = 0.0f;
        #pragma unroll
        for (int r = 0; r < 8; ++r) {
            z0 += zred[r * DD + 2 * tid];
            z1 += zred[r * DD + 2 * tid + 1];
        }
        WS2[128 * WSTR + tid] = pk2(z0, z1);
    }
    for (int idx = tid; idx < 7 * WSTR; idx += NT)
        WS2[129 * WSTR + idx] = 0u;
    __syncthreads();   // zred reads done; WS2 complete

    // ====== Phase 2: out = phiQ x [Sdm | Z], ldmatrix fragments ======
    uint32_t* WQ = stage;               // 2 buffers of [64][QSTR]
    const int s0 = (w & 1) * 32;
    const int m0 = (w >> 1) * 32;

#define STAGEQ(buf_) do {                                                   \
        _Pragma("unroll")                                                   \
        for (int j_ = 0; j_ < 8; ++j_) {                                    \
            const int r_ = lrow + 8 * j_;                                   \
            float p0 = phi_elu1(fmaf(qreg[j_].x, sc4.x, bi4.x));            \
            float p1 = phi_elu1(fmaf(qreg[j_].y, sc4.y, bi4.y));            \
            float p2 = phi_elu1(fmaf(qreg[j_].z, sc4.z, bi4.z));            \
            float p3 = phi_elu1(fmaf(qreg[j_].w, sc4.w, bi4.w));            \
            uint2 qu = make_uint2(pk2(p0, p1), pk2(p2, p3));                \
            *(uint2*)((buf_) + r_ * QSTR + 2 * lane) = qu;                  \
        }                                                                   \
    } while (0)

#define PREFQ(cidx) do {                                                    \
        const float* qc_ = qb + (long)(cidx) * 64 * DD;                     \
        _Pragma("unroll")                                                   \
        for (int j_ = 0; j_ < 8; ++j_)                                      \
            qreg[j_] = *(const float4*)(qc_ + (long)(lrow + 8 * j_) * DD + c4); \
    } while (0)

    // ldmatrix base addresses (loop-invariant per lane)
    const uint32_t base_u = smem_u32(sm);
    const uint32_t wq0u   = base_u + WQ_OFF * 4;
    uint32_t aA[2];
    #pragma unroll
    for (int st = 0; st < 2; ++st) {
        const int rowA = s0 + st * 16 + (l & 7) + 8 * ((l >> 3) & 1);
        aA[st] = wq0u + (uint32_t)(rowA * QSTR + 4 * (l >> 4)) * 4u;
    }
    uint32_t bB[2];
    #pragma unroll
    for (int gs = 0; gs < 2; ++gs) {
        const int rowB = m0 + (gs * 2 + (l >> 4)) * 8 + (l & 7);
        bB[gs] = base_u + (uint32_t)(rowB * WSTR + 4 * ((l >> 3) & 1)) * 4u;
    }
    const uint32_t bZ = base_u + (uint32_t)((128 + (l & 7)) * WSTR + 4 * ((l >> 3) & 1)) * 4u;

    STAGEQ(WQ);            // chunk 0 -> buf0
    PREFQ(1);
    __syncthreads();

    for (int chq = 0; chq < BLK / 64; ++chq) {
        const uint32_t abuf = (uint32_t)((chq & 1) * WQ_BUF) * 4u;

        // stage chunk chq+1 first (frees qreg before the mma loop)
        if (chq < BLK / 64 - 1)
            STAGEQ(WQ + ((chq + 1) & 1) * WQ_BUF);

        float accq[2][5][4];
        #pragma unroll
        for (int st = 0; st < 2; ++st)
            #pragma unroll
            for (int mt = 0; mt < 5; ++mt)
                #pragma unroll
                for (int r = 0; r < 4; ++r) accq[st][mt][r] = 0.0f;

        uint32_t A0[2][4], A1[2][4];
        LDSM4(A0[0], aA[0] + abuf);
        LDSM4(A1[0], aA[1] + abuf);

        #pragma unroll
        for (int kk = 0; kk < DD / 16; ++kk) {   // 8 k-steps of 16
            const int cur = kk & 1;
            const uint32_t ko = 32u * kk;
            uint32_t B0[4], B1[4], BZ[2];
            LDSM4(B0, bB[0] + ko);
            LDSM4(B1, bB[1] + ko);
            LDSM2(BZ, bZ + ko);
            if (kk < DD / 16 - 1) {
                LDSM4(A0[cur ^ 1], aA[0] + abuf + ko + 32u);
                LDSM4(A1[cur ^ 1], aA[1] + abuf + ko + 32u);
            }
            mma_f16(accq[0][0], A0[cur], &B0[0]);
            mma_f16(accq[1][0], A1[cur], &B0[0]);
            mma_f16(accq[0][1], A0[cur], &B0[2]);
            mma_f16(accq[1][1], A1[cur], &B0[2]);
            mma_f16(accq[0][2], A0[cur], &B1[0]);
            mma_f16(accq[1][2], A1[cur], &B1[0]);
            mma_f16(accq[0][3], A0[cur], &B1[2]);
            mma_f16(accq[1][3], A1[cur], &B1[2]);
            mma_f16(accq[0][4], A0[cur], BZ);
            mma_f16(accq[1][4], A1[cur], BZ);
        }

        if (chq < BLK / 64 - 2)
            PREFQ(chq + 2);

        // den via shuffle from lane 4g (Z col = 128 -> t==0, c0/c2)
        #pragma unroll
        for (int st = 0; st < 2; ++st) {
            const float z0 = __shfl_sync(0xffffffffu, accq[st][4][0], lane & 28);
            const float z8 = __shfl_sync(0xffffffffu, accq[st][4][2], lane & 28);
            const float i0 = 1.0f / (z0 + EPS_F);
            const float i1 = 1.0f / (z8 + EPS_F);
            const int rr = s0 + st * 16 + g;
            const int r0 = chq * 64 + rr;
            #pragma unroll
            for (int mt = 0; mt < 4; ++mt) {
                const int m = m0 + mt * 8 + 2 * t;
                *(float2*)(ob + (long)r0 * DD + m) =
                    make_float2(accq[st][mt][0] * i0, accq[st][mt][1] * i0);
                *(float2*)(ob + (long)(r0 + 8) * DD + m) =
                    make_float2(accq[st][mt][2] * i1, accq[st][mt][3] * i1);
            }
        }
        __syncthreads();   // mma reads of buf chq&1 done before next restage
    }
}

extern "C" void kernel_launch(void* const* d_in, const int* in_sizes, int n_in,
                              void* d_out, int out_size) {
    const float* q  = (const float*)d_in[0];
    const float* k  = (const float*)d_in[1];
    const float* v  = (const float*)d_in[2];
    const float* sc = (const float*)d_in[3];
    const float* bi = (const float*)d_in[4];
    float* out = (float*)d_out;

    cudaFuncSetAttribute(lin_attn_lt,
                         cudaFuncAttributeMaxDynamicSharedMemorySize, SMEM_BYTES);
    lin_attn_lt<<<NCTA, NT, SMEM_BYTES>>>(q, k, v, sc, bi, out);
}

// round 17
// speedup vs baseline: 1.0287x; 1.0287x over previous
#include <cuda_runtime.h>
#include <cuda_fp16.h>
#include <cstdint>

// Problem shape (fixed by the dataset instance)
#define BB   2
#define HH   32
#define SS   4096
#define DD   128
#define BLK  512
#define NB   (SS / BLK)          // 8
#define NCTA (BB * HH * NB)      // 512
#define NT   256
#define EPS_F 1e-6f

// Phase-1 staging: plain row-major fp16 [s][cols], 68 words (136 halves) per row
#define PST    68                           // words per s-row (272 B; 68%32==4)
#define P1ROWS 32                           // widened chunk: 32 s-rows
#define KV_TILE (P1ROWS * PST)              // 2176 words per tile (K or V)
#define BUF_WORDS (2 * KV_TILE)             // 4352 words per buffer
#define BUF_BYTES (BUF_WORDS * 4)           // 17408
#define KSOFF (16 * PST * 4)                // byte offset of 2nd k=16 group
// Phase-2 ldmatrix tiles (word = half2 pair along d, d contiguous)
#define WSTR 68    // WS2 [136][WSTR]: rows m (128=Z, 129..135=0)
#define QSTR 68    // WQ  [64][QSTR] x2 buffers

#define WS2_OFF 0
#define WQ_OFF  (136 * WSTR)                // 9248
#define WQ_BUF  (64 * QSTR)                 // 4352 words per buffer
#define SMEM_WORDS (WQ_OFF + 2 * WQ_BUF)    // 17952 (phase-1 2*4352 fits exactly)
#define SMEM_BYTES (SMEM_WORDS * 4)         // 71808 B -> 2 CTAs/SM

__device__ __forceinline__ float phi_elu1(float y) {
    return y > 0.0f ? y + 1.0f : __expf(y);
}

__device__ __forceinline__ uint32_t pk2(float lo, float hi) {
    __half2 h = __floats2half2_rn(lo, hi);
    return *reinterpret_cast<uint32_t*>(&h);
}

__device__ __forceinline__ uint32_t smem_u32(const void* p) {
    uint32_t a;
    asm("{ .reg .u64 t; cvta.to.shared.u64 t, %1; cvt.u32.u64 %0, t; }"
        : "=r"(a) : "l"(p));
    return a;
}

__device__ __forceinline__ void mma_f16(float* c, const uint32_t* a, const uint32_t* b) {
    asm volatile(
        "mma.sync.aligned.m16n8k16.row.col.f32.f16.f16.f32 "
        "{%0,%1,%2,%3}, {%4,%5,%6,%7}, {%8,%9}, {%0,%1,%2,%3};\n"
        : "+f"(c[0]), "+f"(c[1]), "+f"(c[2]), "+f"(c[3])
        : "r"(a[0]), "r"(a[1]), "r"(a[2]), "r"(a[3]), "r"(b[0]), "r"(b[1]));
}

#define LDSM4(r, addr)                                                      \
    asm volatile("ldmatrix.sync.aligned.m8n8.x4.shared.b16 "                \
                 "{%0,%1,%2,%3}, [%4];"                                     \
                 : "=r"((r)[0]), "=r"((r)[1]), "=r"((r)[2]), "=r"((r)[3])   \
                 : "r"(addr))
#define LDSM4T(r, addr)                                                     \
    asm volatile("ldmatrix.sync.aligned.m8n8.x4.trans.shared.b16 "          \
                 "{%0,%1,%2,%3}, [%4];"                                     \
                 : "=r"((r)[0]), "=r"((r)[1]), "=r"((r)[2]), "=r"((r)[3])   \
                 : "r"(addr))
#define LDSM2(r, addr)                                                      \
    asm volatile("ldmatrix.sync.aligned.m8n8.x2.shared.b16 "                \
                 "{%0,%1}, [%2];"                                           \
                 : "=r"((r)[0]), "=r"((r)[1])                               \
                 : "r"(addr))

extern "C" __global__ void __launch_bounds__(NT, 2)
lin_attn_w32(const float* __restrict__ q,
             const float* __restrict__ k,
             const float* __restrict__ v,
             const float* __restrict__ sc,
             const float* __restrict__ bi,
             float* __restrict__ out)
{
    extern __shared__ uint32_t sm[];
    uint32_t* WS2   = sm + WS2_OFF;     // [136][WSTR] half2 along d; row 128 = Z
    uint32_t* stage = sm + WQ_OFF;      // phase1: 2 x (K tile + V tile); phase2: WQ x2

    const int tid  = threadIdx.x;
    const int lane = tid & 31;
    const int w    = tid >> 5;          // warp 0..7
    const int g    = lane >> 2;         // 0..7
    const int t    = lane & 3;          // 0..3

    const int c  = blockIdx.x;
    const int n  = c % NB;
    const int bh = c / NB;
    const int h  = bh % HH;
    const long gbase = ((long)bh * SS + (long)n * BLK) * DD;

    const float* qb = q + gbase;
    const float* kb = k + gbase;
    const float* vb = v + gbase;
    float*       ob = out + gbase;

    const int lrow = w;                 // producer warp index
    const int c4   = lane * 4;          // producer d-columns c4..c4+3
    const float4 sc4 = *(const float4*)(sc + h * DD + c4);
    const float4 bi4 = *(const float4*)(bi + h * DD + c4);

    // ====== Phase 1: S^T[m][d] = V^T x phiK  (A = V^T, B = phiK, k = s) ====
    const int wa = w & 1;               // m half (64)
    const int wb = w >> 1;              // d quarter (32)

    float acc[4][4][4];                 // [mt][dt][c]
    #pragma unroll
    for (int a = 0; a < 4; ++a)
        #pragma unroll
        for (int b = 0; b < 4; ++b)
            #pragma unroll
            for (int r = 0; r < 4; ++r) acc[a][b][r] = 0.0f;

    float4 zacc = make_float4(0.f, 0.f, 0.f, 0.f);
    // prefetch registers: 4 K rows + 4 V rows per warp (rows 2w,2w+1,16+2w,17+2w)
    float4 kv0, kv1, kv2, kv3, vv0, vv1, vv2, vv3;

#define LOADCH(ch) do {                                                     \
        const float* kc_ = kb + (long)((ch) * P1ROWS + 2 * lrow) * DD;      \
        const float* vc_ = vb + (long)((ch) * P1ROWS + 2 * lrow) * DD;      \
        kv0 = *(const float4*)(kc_ + c4);                                   \
        kv1 = *(const float4*)(kc_ + DD + c4);                              \
        kv2 = *(const float4*)(kc_ + 16 * DD + c4);                         \
        kv3 = *(const float4*)(kc_ + 17 * DD + c4);                         \
        vv0 = *(const float4*)(vc_ + c4);                                   \
        vv1 = *(const float4*)(vc_ + DD + c4);                              \
        vv2 = *(const float4*)(vc_ + 16 * DD + c4);                         \
        vv3 = *(const float4*)(vc_ + 17 * DD + c4);                         \
    } while (0)

    // plain row-major fp16 staging: row s, halves d contiguous (word = d,d+1)
#define STROW(pk_, r_, kvr_) do {                                           \
        float a0 = phi_elu1(fmaf((kvr_).x, sc4.x, bi4.x));                  \
        float a1 = phi_elu1(fmaf((kvr_).y, sc4.y, bi4.y));                  \
        float a2 = phi_elu1(fmaf((kvr_).z, sc4.z, bi4.z));                  \
        float a3 = phi_elu1(fmaf((kvr_).w, sc4.w, bi4.w));                  \
        zacc.x += a0; zacc.y += a1; zacc.z += a2; zacc.w += a3;             \
        *(uint2*)((pk_) + (r_) * PST + 2 * lane) =                          \
            make_uint2(pk2(a0, a1), pk2(a2, a3));                           \
    } while (0)

#define STVROW(pv_, r_, vvr_)                                               \
        *(uint2*)((pv_) + (r_) * PST + 2 * lane) =                          \
            make_uint2(pk2((vvr_).x, (vvr_).y), pk2((vvr_).z, (vvr_).w))

#define STORECH(pk_, pv_) do {                                              \
        STROW(pk_, 2 * lrow,      kv0);                                     \
        STROW(pk_, 2 * lrow + 1,  kv1);                                     \
        STROW(pk_, 16 + 2 * lrow, kv2);                                     \
        STROW(pk_, 17 + 2 * lrow, kv3);                                     \
        STVROW(pv_, 2 * lrow,      vv0);                                    \
        STVROW(pv_, 2 * lrow + 1,  vv1);                                    \
        STVROW(pv_, 16 + 2 * lrow, vv2);                                    \
        STVROW(pv_, 17 + 2 * lrow, vv3);                                    \
    } while (0)

    // ldmatrix.trans base addresses (bytes), lane-invariant parts (proven R16):
    //  A (V, [s][m]): lane l: s-row = (l>>4)*8 + (l&7),
    //                 m-col  = wa*64 + mt*16 + ((l>>3)&1)*8
    //  B (phiK,[s][d]): lane l: s-row = ((l>>3)&1)*8 + (l&7),
    //                 d-col  = wb*32 + (l>>4)*8  (+16 per Bf group)
    const uint32_t stage_b = smem_u32(stage);
    const int l = lane;
    const uint32_t aAb = stage_b + (uint32_t)(KV_TILE * 4)                  // V tile
                       + (uint32_t)(((l >> 4) * 8 + (l & 7)) * (PST * 4))
                       + (uint32_t)((wa * 64 + ((l >> 3) & 1) * 8) * 2);
    const uint32_t bBb = stage_b
                       + (uint32_t)((((l >> 3) & 1) * 8 + (l & 7)) * (PST * 4))
                       + (uint32_t)((wb * 32 + (l >> 4) * 8) * 2);

    LOADCH(0);
    STORECH(stage, stage + KV_TILE);
    LOADCH(1);
    __syncthreads();

    for (int ch = 0; ch < BLK / P1ROWS; ++ch) {      // 16 chunks of 32 rows
        const int p = ch & 1;

        if (ch < BLK / P1ROWS - 1) {
            uint32_t* npk = stage + (p ^ 1) * BUF_WORDS;
            STORECH(npk, npk + KV_TILE);
        }
        if (ch < BLK / P1ROWS - 2) LOADCH(ch + 2);

        const uint32_t pb = (uint32_t)(p * BUF_BYTES);
        #pragma unroll
        for (int ks = 0; ks < 2; ++ks) {             // two k=16 groups
            const uint32_t ko = pb + (uint32_t)(ks * KSOFF);
            uint32_t Bf[2][4];
            LDSM4T(Bf[0], bBb + ko);
            LDSM4T(Bf[1], bBb + ko + 32u);
            #pragma unroll
            for (int mt = 0; mt < 4; ++mt) {
                uint32_t A[4];
                LDSM4T(A, aAb + ko + (uint32_t)(mt * 32));
                mma_f16(acc[mt][0], A, &Bf[0][0]);
                mma_f16(acc[mt][1], A, &Bf[0][2]);
                mma_f16(acc[mt][2], A, &Bf[1][0]);
                mma_f16(acc[mt][3], A, &Bf[1][2]);
            }
        }
        __syncthreads();
    }

    // ===== epilogue: S^T -> WS2[m][d-halves] (c0,c1 are d-adjacent) =====
    #pragma unroll
    for (int mt = 0; mt < 4; ++mt) {
        const int m = wa * 64 + mt * 16 + g;
        #pragma unroll
        for (int dt = 0; dt < 4; ++dt) {
            const int dw = wb * 16 + dt * 4 + t;       // d word index
            WS2[m       * WSTR + dw] = pk2(acc[mt][dt][0], acc[mt][dt][1]);
            WS2[(m + 8) * WSTR + dw] = pk2(acc[mt][dt][2], acc[mt][dt][3]);
        }
    }

    // prefetch Q chunk 0 (overlaps Z reduction)
    float4 qreg[8];
    #pragma unroll
    for (int j = 0; j < 8; ++j)
        qreg[j] = *(const float4*)(qb + (long)(lrow + 8 * j) * DD + c4);

    // reduce Z -> WS2 row 128 ; zero rows 129..135
    float* zred = (float*)stage;
    *(float4*)(zred + lrow * DD + c4) = zacc;
    __syncthreads();
    if (tid < 64) {
        float z0 = 0.0f, z1 = 0.0f;
        #pragma unroll
        for (int r = 0; r < 8; ++r) {
            z0 += zred[r * DD + 2 * tid];
            z1 += zred[r * DD + 2 * tid + 1];
        }
        WS2[128 * WSTR + tid] = pk2(z0, z1);
    }
    for (int idx = tid; idx < 7 * WSTR; idx += NT)
        WS2[129 * WSTR + idx] = 0u;
    __syncthreads();   // zred reads done; WS2 complete

    // ====== Phase 2: out = phiQ x [Sdm | Z], ldmatrix fragments ======
    uint32_t* WQ = stage;               // 2 buffers of [64][QSTR]
    const int s0 = (w & 1) * 32;
    const int m0 = (w >> 1) * 32;

#define STAGEQ(buf_) do {                                                   \
        _Pragma("unroll")                                                   \
        for (int j_ = 0; j_ < 8; ++j_) {                                    \
            const int r_ = lrow + 8 * j_;                                   \
            float p0 = phi_elu1(fmaf(qreg[j_].x, sc4.x, bi4.x));            \
            float p1 = phi_elu1(fmaf(qreg[j_].y, sc4.y, bi4.y));            \
            float p2 = phi_elu1(fmaf(qreg[j_].z, sc4.z, bi4.z));            \
            float p3 = phi_elu1(fmaf(qreg[j_].w, sc4.w, bi4.w));            \
            uint2 qu = make_uint2(pk2(p0, p1), pk2(p2, p3));                \
            *(uint2*)((buf_) + r_ * QSTR + 2 * lane) = qu;                  \
        }                                                                   \
    } while (0)

#define PREFQ(cidx) do {                                                    \
        const float* qc_ = qb + (long)(cidx) * 64 * DD;                     \
        _Pragma("unroll")                                                   \
        for (int j_ = 0; j_ < 8; ++j_)                                      \
            qreg[j_] = *(const float4*)(qc_ + (long)(lrow + 8 * j_) * DD + c4); \
    } while (0)

    // ldmatrix base addresses (loop-invariant per lane)
    const uint32_t base_u = smem_u32(sm);
    const uint32_t wq0u   = base_u + WQ_OFF * 4;
    uint32_t aA[2];
    #pragma unroll
    for (int st = 0; st < 2; ++st) {
        const int rowA = s0 + st * 16 + (l & 7) + 8 * ((l >> 3) & 1);
        aA[st] = wq0u + (uint32_t)(rowA * QSTR + 4 * (l >> 4)) * 4u;
    }
    uint32_t bB[2];
    #pragma unroll
    for (int gs = 0; gs < 2; ++gs) {
        const int rowB = m0 + (gs * 2 + (l >> 4)) * 8 + (l & 7);
        bB[gs] = base_u + (uint32_t)(rowB * WSTR + 4 * ((l >> 3) & 1)) * 4u;
    }
    const uint32_t bZ = base_u + (uint32_t)((128 + (l & 7)) * WSTR + 4 * ((l >> 3) & 1)) * 4u;

    STAGEQ(WQ);            // chunk 0 -> buf0
    PREFQ(1);
    __syncthreads();

    for (int chq = 0; chq < BLK / 64; ++chq) {
        const uint32_t abuf = (uint32_t)((chq & 1) * WQ_BUF) * 4u;

        // stage chunk chq+1 first (frees qreg before the mma loop)
        if (chq < BLK / 64 - 1)
            STAGEQ(WQ + ((chq + 1) & 1) * WQ_BUF);

        float accq[2][5][4];
        #pragma unroll
        for (int st = 0; st < 2; ++st)
            #pragma unroll
            for (int mt = 0; mt < 5; ++mt)
                #pragma unroll
                for (int r = 0; r < 4; ++r) accq[st][mt][r] = 0.0f;

        uint32_t A0[2][4], A1[2][4];
        LDSM4(A0[0], aA[0] + abuf);
        LDSM4(A1[0], aA[1] + abuf);

        #pragma unroll
        for (int kk = 0; kk < DD / 16; ++kk) {   // 8 k-steps of 16
            const int cur = kk & 1;
            const uint32_t ko = 32u * kk;
            uint32_t B0[4], B1[4], BZ[2];
            LDSM4(B0, bB[0] + ko);
            LDSM4(B1, bB[1] + ko);
            LDSM2(BZ, bZ + ko);
            if (kk < DD / 16 - 1) {
                LDSM4(A0[cur ^ 1], aA[0] + abuf + ko + 32u);
                LDSM4(A1[cur ^ 1], aA[1] + abuf + ko + 32u);
            }
            mma_f16(accq[0][0], A0[cur], &B0[0]);
            mma_f16(accq[1][0], A1[cur], &B0[0]);
            mma_f16(accq[0][1], A0[cur], &B0[2]);
            mma_f16(accq[1][1], A1[cur], &B0[2]);
            mma_f16(accq[0][2], A0[cur], &B1[0]);
            mma_f16(accq[1][2], A1[cur], &B1[0]);
            mma_f16(accq[0][3], A0[cur], &B1[2]);
            mma_f16(accq[1][3], A1[cur], &B1[2]);
            mma_f16(accq[0][4], A0[cur], BZ);
            mma_f16(accq[1][4], A1[cur], BZ);
        }

        if (chq < BLK / 64 - 2)
            PREFQ(chq + 2);

        // den via shuffle from lane 4g (Z col = 128 -> t==0, c0/c2)
        #pragma unroll
        for (int st = 0; st < 2; ++st) {
            const float z0 = __shfl_sync(0xffffffffu, accq[st][4][0], lane & 28);
            const float z8 = __shfl_sync(0xffffffffu, accq[st][4][2], lane & 28);
            const float i0 = 1.0f / (z0 + EPS_F);
            const float i1 = 1.0f / (z8 + EPS_F);
            const int rr = s0 + st * 16 + g;
            const int r0 = chq * 64 + rr;
            #pragma unroll
            for (int mt = 0; mt < 4; ++mt) {
                const int m = m0 + mt * 8 + 2 * t;
                *(float2*)(ob + (long)r0 * DD + m) =
                    make_float2(accq[st][mt][0] * i0, accq[st][mt][1] * i0);
                *(float2*)(ob + (long)(r0 + 8) * DD + m) =
                    make_float2(accq[st][mt][2] * i1, accq[st][mt][3] * i1);
            }
        }
        __syncthreads();   // mma reads of buf chq&1 done before next restage
    }
}

extern "C" void kernel_launch(void* const* d_in, const int* in_sizes, int n_in,
                              void* d_out, int out_size) {
    const float* q  = (const float*)d_in[0];
    const float* k  = (const float*)d_in[1];
    const float* v  = (const float*)d_in[2];
    const float* sc = (const float*)d_in[3];
    const float* bi = (const float*)d_in[4];
    float* out = (float*)d_out;

    cudaFuncSetAttribute(lin_attn_w32,
                         cudaFuncAttributeMaxDynamicSharedMemorySize, SMEM_BYTES);
    lin_attn_w32<<<NCTA, NT, SMEM_BYTES>>>(q, k, v, sc, bi, out);
}